// round 1
// baseline (speedup 1.0000x reference)
#include <cuda_runtime.h>
#include <cstdint>

// Problem constants (shapes fixed by the reference).
#define D 96            // D_IN == D_OUT == 96
#define MAXN 50000
#define MAXE 800000

// Scratch: device globals (no cudaMalloc allowed).
__device__ float g_agg[(size_t)MAXN * D];   // 19.2 MB, sum of neighbor features
__device__ float g_deg[MAXN];               // in-degree, then inverted in-place

// ---------------------------------------------------------------------------
// 0) zero scratch
// ---------------------------------------------------------------------------
__global__ void zero_kernel(int n_agg4, int n_deg) {
    int idx = blockIdx.x * blockDim.x + threadIdx.x;
    int stride = gridDim.x * blockDim.x;
    float4* a4 = reinterpret_cast<float4*>(g_agg);
    for (int i = idx; i < n_agg4; i += stride)
        a4[i] = make_float4(0.f, 0.f, 0.f, 0.f);
    for (int i = idx; i < n_deg; i += stride)
        g_deg[i] = 0.f;
}

// ---------------------------------------------------------------------------
// 1) scatter: agg[dst] += x[src]; deg[dst] += 1
//    blockDim = (24, 8): threadIdx.x picks one of 24 float4 chunks of the
//    96-float row; threadIdx.y picks one of 8 edges per block.
//    Uses sm_90+ vectorized reduction (red.global.add.v4.f32): 4x fewer
//    L2 atomic ops than scalar atomicAdd.
// ---------------------------------------------------------------------------
__global__ __launch_bounds__(192) void scatter_kernel(
    const float* __restrict__ x, const int* __restrict__ ei, int E)
{
    int e = blockIdx.x * 8 + threadIdx.y;
    if (e >= E) return;
    int c = threadIdx.x;                 // 0..23 (float4 chunk)
    int src = __ldg(ei + e);             // row 0 of edge_index
    int dst = __ldg(ei + E + e);         // row 1 of edge_index

    float4 v = *reinterpret_cast<const float4*>(x + (size_t)src * D + c * 4);
    float* p = g_agg + (size_t)dst * D + c * 4;
    asm volatile("red.global.add.v4.f32 [%0], {%1,%2,%3,%4};"
                 :: "l"(p), "f"(v.x), "f"(v.y), "f"(v.z), "f"(v.w)
                 : "memory");
    if (c == 0) atomicAdd(g_deg + dst, 1.0f);
}

// ---------------------------------------------------------------------------
// 2) invert degree once (deg := 1/max(deg,1)) so the GEMM hot loop
//    multiplies instead of dividing (no MUFU in the mainloop).
// ---------------------------------------------------------------------------
__global__ void recip_kernel(int n) {
    int i = blockIdx.x * blockDim.x + threadIdx.x;
    if (i < n) g_deg[i] = 1.0f / fmaxf(g_deg[i], 1.0f);
}

// ---------------------------------------------------------------------------
// 3) fused GEMM: out = relu( (agg * invdeg) @ Wl^T + x @ Wr^T + bl )
//    Block: 64 nodes x full 96 outputs. 256 threads, 4x6 register tile.
//    Two phases (p=0: agg/Wl, p=1: x/Wr) accumulate into the same regs.
// ---------------------------------------------------------------------------
__global__ __launch_bounds__(256) void fused_gemm_kernel(
    const float* __restrict__ x,
    const float* __restrict__ Wl, const float* __restrict__ bl,
    const float* __restrict__ Wr,
    float* __restrict__ out, int N)
{
    __shared__ float As[16][65];   // As[k][m]  (A tile transposed)
    __shared__ float Ws[16][97];   // Ws[k][n]  = W[n][k0+k]

    const int tid = threadIdx.x;
    const int tx = tid & 15;       // n-group: outputs tx*6 .. tx*6+5
    const int ty = tid >> 4;       // m-group: nodes   ty*4 .. ty*4+3
    const int m0 = blockIdx.x * 64;

    float acc[4][6];
#pragma unroll
    for (int i = 0; i < 4; ++i)
#pragma unroll
        for (int j = 0; j < 6; ++j) acc[i][j] = 0.f;

    // A-tile load indices: each thread loads one float4 along k.
    const int lm = tid >> 2;         // 0..63 (node within tile)
    const int lk = (tid & 3) << 2;   // 0,4,8,12 (k offset)

#pragma unroll
    for (int p = 0; p < 2; ++p) {
        const float* __restrict__ A = p ? x : g_agg;
        const float* __restrict__ W = p ? Wr : Wl;

        for (int k0 = 0; k0 < D; k0 += 16) {
            // --- load A tile (64 x 16) ---
            {
                int node = m0 + lm;
                float4 v = make_float4(0.f, 0.f, 0.f, 0.f);
                if (node < N) {
                    v = *reinterpret_cast<const float4*>(A + (size_t)node * D + k0 + lk);
                    if (p == 0) {
                        float inv = g_deg[node];
                        v.x *= inv; v.y *= inv; v.z *= inv; v.w *= inv;
                    }
                }
                As[lk + 0][lm] = v.x;
                As[lk + 1][lm] = v.y;
                As[lk + 2][lm] = v.z;
                As[lk + 3][lm] = v.w;
            }
            // --- load W tile (96 x 16), stored as Ws[k][n] ---
#pragma unroll
            for (int i = 0; i < 6; ++i) {
                int l = tid + i * 256;      // 0..1535
                int n = l >> 4;
                int k = l & 15;
                Ws[k][n] = W[n * D + k0 + k];
            }
            __syncthreads();

            // --- compute ---
#pragma unroll
            for (int k = 0; k < 16; ++k) {
                float a[4], w[6];
#pragma unroll
                for (int i = 0; i < 4; ++i) a[i] = As[k][ty * 4 + i];
#pragma unroll
                for (int j = 0; j < 6; ++j) w[j] = Ws[k][tx * 6 + j];
#pragma unroll
                for (int i = 0; i < 4; ++i)
#pragma unroll
                    for (int j = 0; j < 6; ++j)
                        acc[i][j] = fmaf(a[i], w[j], acc[i][j]);
            }
            __syncthreads();
        }
    }

    // --- epilogue: bias + relu + store ---
#pragma unroll
    for (int i = 0; i < 4; ++i) {
        int node = m0 + ty * 4 + i;
        if (node < N) {
#pragma unroll
            for (int j = 0; j < 6; ++j) {
                int n = tx * 6 + j;
                out[(size_t)node * D + n] = fmaxf(acc[i][j] + __ldg(bl + n), 0.f);
            }
        }
    }
}

// ---------------------------------------------------------------------------
// kernel_launch
// Inputs (metadata order): x [N*96] f32, edge_index [2*E] i32,
//                          Wl [96*96] f32, bl [96] f32, Wr [96*96] f32
// Output: [N*96] f32
// ---------------------------------------------------------------------------
extern "C" void kernel_launch(void* const* d_in, const int* in_sizes, int n_in,
                              void* d_out, int out_size)
{
    const float* x  = (const float*)d_in[0];
    const int*   ei = (const int*)  d_in[1];
    const float* Wl = (const float*)d_in[2];
    const float* bl = (const float*)d_in[3];
    const float* Wr = (const float*)d_in[4];
    float* out = (float*)d_out;

    const int N = in_sizes[0] / D;
    const int E = in_sizes[1] / 2;

    // 0) zero scratch
    zero_kernel<<<2048, 256>>>((N * D) / 4, N);

    // 1) scatter-add with vectorized L2 reductions
    dim3 sblk(24, 8);
    scatter_kernel<<<(E + 7) / 8, sblk>>>(x, ei, E);

    // 2) invert degree
    recip_kernel<<<(N + 255) / 256, 256>>>(N);

    // 3) fused dual-GEMM + bias + relu
    fused_gemm_kernel<<<(N + 63) / 64, 256>>>(x, Wl, bl, Wr, out, N);
}

// round 2
// speedup vs baseline: 1.0297x; 1.0297x over previous
#include <cuda_runtime.h>
#include <cstdint>

// Problem constants (shapes fixed by the reference).
#define D 96            // D_IN == D_OUT == 96
#define MAXN 50000
#define MAXE 800000

// Scratch: device globals (no cudaMalloc allowed).
__device__ float g_agg[(size_t)MAXN * D];   // 19.2 MB, sum of neighbor features
__device__ float g_deg[MAXN];               // in-degree, then inverted in-place

// ---------------------------------------------------------------------------
// f32x2 packed helpers (sm_103a): 2 fp32 FMAs per instruction.
// ---------------------------------------------------------------------------
__device__ __forceinline__ unsigned long long f32x2_dup(float s) {
    unsigned long long d;
    asm("mov.b64 %0, {%1, %1};" : "=l"(d) : "f"(s));
    return d;
}
__device__ __forceinline__ unsigned long long ffma2(
    unsigned long long a, unsigned long long b, unsigned long long c) {
    unsigned long long d;
    asm("fma.rn.f32x2 %0, %1, %2, %3;" : "=l"(d) : "l"(a), "l"(b), "l"(c));
    return d;
}
__device__ __forceinline__ void f32x2_unpack(unsigned long long v, float& lo, float& hi) {
    asm("mov.b64 {%0, %1}, %2;" : "=f"(lo), "=f"(hi) : "l"(v));
}

// ---------------------------------------------------------------------------
// 0) zero scratch
// ---------------------------------------------------------------------------
__global__ void zero_kernel(int n_agg4, int n_deg) {
    int idx = blockIdx.x * blockDim.x + threadIdx.x;
    int stride = gridDim.x * blockDim.x;
    float4* a4 = reinterpret_cast<float4*>(g_agg);
    for (int i = idx; i < n_agg4; i += stride)
        a4[i] = make_float4(0.f, 0.f, 0.f, 0.f);
    for (int i = idx; i < n_deg; i += stride)
        g_deg[i] = 0.f;
}

// ---------------------------------------------------------------------------
// 1) scatter: agg[dst] += x[src]; deg[dst] += 1   (red.global.add.v4.f32)
// ---------------------------------------------------------------------------
__global__ __launch_bounds__(192) void scatter_kernel(
    const float* __restrict__ x, const int* __restrict__ ei, int E)
{
    int e = blockIdx.x * 8 + threadIdx.y;
    if (e >= E) return;
    int c = threadIdx.x;                 // 0..23 (float4 chunk)
    int src = __ldg(ei + e);             // row 0 of edge_index
    int dst = __ldg(ei + E + e);         // row 1 of edge_index

    float4 v = *reinterpret_cast<const float4*>(x + (size_t)src * D + c * 4);
    float* p = g_agg + (size_t)dst * D + c * 4;
    asm volatile("red.global.add.v4.f32 [%0], {%1,%2,%3,%4};"
                 :: "l"(p), "f"(v.x), "f"(v.y), "f"(v.z), "f"(v.w)
                 : "memory");
    if (c == 0) atomicAdd(g_deg + dst, 1.0f);
}

// ---------------------------------------------------------------------------
// 2) invert degree once (deg := 1/max(deg,1))
// ---------------------------------------------------------------------------
__global__ void recip_kernel(int n) {
    int i = blockIdx.x * blockDim.x + threadIdx.x;
    if (i < n) g_deg[i] = 1.0f / fmaxf(g_deg[i], 1.0f);
}

// ---------------------------------------------------------------------------
// 3) fused GEMM via packed fma.rn.f32x2:
//      out = relu( (agg * invdeg) @ Wl^T + x @ Wr^T + bl )
//    Block: 128 nodes x 96 outputs, 192 threads.
//    Thread (ty 0..15, tx 0..11):
//      nodes   m = m0 + ty*2 + 32*p + {0,1},  p = 0..3  (4 f32x2 node-pairs)
//      outputs n = tx*2 + 24*q + {0,1},       q = 0..3  (8 outputs)
//    Per k-step: 4 LDS.64 (a-pairs) + 4 LDS.64 (w float2) + 8 dup movs
//                + 32 FFMA2 (= 64 fp32 FMA).
// ---------------------------------------------------------------------------
__global__ __launch_bounds__(192) void fused_gemm_kernel(
    const float* __restrict__ x,
    const float* __restrict__ Wl, const float* __restrict__ bl,
    const float* __restrict__ Wr,
    float* __restrict__ out, int N)
{
    __shared__ float As[16][132];   // As[k][m], row 528 B (16B aligned)
    __shared__ float Ws[16][100];   // Ws[k][n], row 400 B (8B aligned)

    const int tid = threadIdx.x;
    const int ty  = tid & 15;       // node-pair group
    const int tx  = tid >> 4;       // 0..11, output group
    const int m0  = blockIdx.x * 128;

    unsigned long long acc[4][8];
#pragma unroll
    for (int p = 0; p < 4; ++p)
#pragma unroll
        for (int j = 0; j < 8; ++j) acc[p][j] = 0ull;

#pragma unroll 1
    for (int t = 0; t < 12; ++t) {
        const bool  ph0 = (t < 6);
        const float* __restrict__ A = ph0 ? g_agg : x;
        const float* __restrict__ W = ph0 ? Wl : Wr;
        const int k0 = (ph0 ? t : t - 6) * 16;

        // --- load A tile (128 nodes x 16 k), float4 per element-group ---
        for (int l = tid; l < 512; l += 192) {
            int m  = l >> 2;
            int kq = (l & 3) << 2;
            int node = m0 + m;
            float4 v = make_float4(0.f, 0.f, 0.f, 0.f);
            if (node < N) {
                v = *reinterpret_cast<const float4*>(A + (size_t)node * D + k0 + kq);
                if (ph0) {
                    float inv = g_deg[node];
                    v.x *= inv; v.y *= inv; v.z *= inv; v.w *= inv;
                }
            }
            As[kq + 0][m] = v.x;
            As[kq + 1][m] = v.y;
            As[kq + 2][m] = v.z;
            As[kq + 3][m] = v.w;
        }
        // --- load W tile (96 n x 16 k) ---
        for (int l = tid; l < 1536; l += 192) {
            int k = l & 15;
            int n = l >> 4;
            Ws[k][n] = W[n * D + k0 + k];
        }
        __syncthreads();

        // --- compute ---
#pragma unroll
        for (int k = 0; k < 16; ++k) {
            unsigned long long a[4];
#pragma unroll
            for (int p = 0; p < 4; ++p)
                a[p] = *reinterpret_cast<const unsigned long long*>(
                           &As[k][ty * 2 + 32 * p]);

            unsigned long long w[8];
#pragma unroll
            for (int q = 0; q < 4; ++q) {
                float2 wv = *reinterpret_cast<const float2*>(
                                &Ws[k][tx * 2 + 24 * q]);
                w[2 * q]     = f32x2_dup(wv.x);
                w[2 * q + 1] = f32x2_dup(wv.y);
            }
#pragma unroll
            for (int p = 0; p < 4; ++p)
#pragma unroll
                for (int j = 0; j < 8; ++j)
                    acc[p][j] = ffma2(a[p], w[j], acc[p][j]);
        }
        __syncthreads();
    }

    // --- epilogue: bias + relu + float2 stores ---
#pragma unroll
    for (int p = 0; p < 4; ++p) {
        int mA = m0 + ty * 2 + 32 * p;  // even node (lo lane)
        int mB = mA + 1;                // odd node (hi lane)
#pragma unroll
        for (int q = 0; q < 4; ++q) {
            int n = tx * 2 + 24 * q;
            float b0 = __ldg(bl + n);
            float b1 = __ldg(bl + n + 1);
            float v0lo, v0hi, v1lo, v1hi;
            f32x2_unpack(acc[p][2 * q],     v0lo, v0hi);  // output n
            f32x2_unpack(acc[p][2 * q + 1], v1lo, v1hi);  // output n+1
            if (mA < N) {
                float2 o = make_float2(fmaxf(v0lo + b0, 0.f),
                                       fmaxf(v1lo + b1, 0.f));
                *reinterpret_cast<float2*>(out + (size_t)mA * D + n) = o;
            }
            if (mB < N) {
                float2 o = make_float2(fmaxf(v0hi + b0, 0.f),
                                       fmaxf(v1hi + b1, 0.f));
                *reinterpret_cast<float2*>(out + (size_t)mB * D + n) = o;
            }
        }
    }
}

// ---------------------------------------------------------------------------
// kernel_launch
// Inputs (metadata order): x [N*96] f32, edge_index [2*E] i32,
//                          Wl [96*96] f32, bl [96] f32, Wr [96*96] f32
// Output: [N*96] f32
// ---------------------------------------------------------------------------
extern "C" void kernel_launch(void* const* d_in, const int* in_sizes, int n_in,
                              void* d_out, int out_size)
{
    const float* x  = (const float*)d_in[0];
    const int*   ei = (const int*)  d_in[1];
    const float* Wl = (const float*)d_in[2];
    const float* bl = (const float*)d_in[3];
    const float* Wr = (const float*)d_in[4];
    float* out = (float*)d_out;

    const int N = in_sizes[0] / D;
    const int E = in_sizes[1] / 2;

    // 0) zero scratch
    zero_kernel<<<2048, 256>>>((N * D) / 4, N);

    // 1) scatter-add with vectorized L2 reductions
    dim3 sblk(24, 8);
    scatter_kernel<<<(E + 7) / 8, sblk>>>(x, ei, E);

    // 2) invert degree
    recip_kernel<<<(N + 255) / 256, 256>>>(N);

    // 3) fused dual-GEMM + bias + relu (f32x2 packed FMA)
    fused_gemm_kernel<<<(N + 127) / 128, 192>>>(x, Wl, bl, Wr, out, N);
}

// round 4
// speedup vs baseline: 1.0950x; 1.0634x over previous
#include <cuda_runtime.h>
#include <cuda_bf16.h>
#include <cstdint>

// Problem constants.
#define D    96      // D_IN == D_OUT
#define K2   192     // concat K = 2*D
#define MAXN 50000

// Scratch (no cudaMalloc allowed). uint4 typing guarantees 16B alignment.
__device__ float g_agg[(size_t)MAXN * D];        // neighbor-sum
__device__ float g_deg[MAXN];                    // degree -> 1/max(deg,1)
__device__ uint4 g_Bhi4[(D * K2 * 2) / 16];      // [96][192] bf16 Wcat hi
__device__ uint4 g_Blo4[(D * K2 * 2) / 16];      // [96][192] bf16 Wcat lo

// ---------------------------------------------------------------------------
// helpers
// ---------------------------------------------------------------------------
__device__ __forceinline__ uint32_t smem_u32(const void* p) {
    uint32_t a;
    asm("{ .reg .u64 t; cvta.to.shared.u64 t, %1; cvt.u32.u64 %0, t; }"
        : "=r"(a) : "l"(p));
    return a;
}

// pack two f32 into bf16x2 (lo half = a, hi half = b), round-to-nearest
__device__ __forceinline__ uint32_t pack_bf16x2(float a, float b) {
    uint32_t r;
    asm("cvt.rn.bf16x2.f32 %0, %1, %2;" : "=r"(r) : "f"(b), "f"(a));
    return r;
}

#define LDSM_X4(r, addr)                                                      \
    asm volatile("ldmatrix.sync.aligned.m8n8.x4.shared.b16 "                  \
                 "{%0,%1,%2,%3}, [%4];"                                       \
                 : "=r"((r)[0]), "=r"((r)[1]), "=r"((r)[2]), "=r"((r)[3])     \
                 : "r"(addr))

__device__ __forceinline__ void mma_bf16(float* c, const uint32_t* a,
                                         uint32_t b0, uint32_t b1) {
    asm volatile(
        "mma.sync.aligned.m16n8k16.row.col.f32.bf16.bf16.f32 "
        "{%0,%1,%2,%3}, {%4,%5,%6,%7}, {%8,%9}, {%0,%1,%2,%3};"
        : "+f"(c[0]), "+f"(c[1]), "+f"(c[2]), "+f"(c[3])
        : "r"(a[0]), "r"(a[1]), "r"(a[2]), "r"(a[3]), "r"(b0), "r"(b1));
}

// ---------------------------------------------------------------------------
// 0) zero scratch
// ---------------------------------------------------------------------------
__global__ void zero_kernel(int n_agg4, int n_deg) {
    int idx = blockIdx.x * blockDim.x + threadIdx.x;
    int stride = gridDim.x * blockDim.x;
    float4* a4 = reinterpret_cast<float4*>(g_agg);
    for (int i = idx; i < n_agg4; i += stride)
        a4[i] = make_float4(0.f, 0.f, 0.f, 0.f);
    for (int i = idx; i < n_deg; i += stride)
        g_deg[i] = 0.f;
}

// ---------------------------------------------------------------------------
// 1) scatter: agg[dst] += x[src]; deg[dst] += 1   (red.global.add.v4.f32)
// ---------------------------------------------------------------------------
__global__ __launch_bounds__(192) void scatter_kernel(
    const float* __restrict__ x, const int* __restrict__ ei, int E)
{
    int e = blockIdx.x * 8 + threadIdx.y;
    if (e >= E) return;
    int c = threadIdx.x;                 // 0..23
    int src = __ldg(ei + e);
    int dst = __ldg(ei + E + e);

    float4 v = *reinterpret_cast<const float4*>(x + (size_t)src * D + c * 4);
    float* p = g_agg + (size_t)dst * D + c * 4;
    asm volatile("red.global.add.v4.f32 [%0], {%1,%2,%3,%4};"
                 :: "l"(p), "f"(v.x), "f"(v.y), "f"(v.z), "f"(v.w)
                 : "memory");
    if (c == 0) atomicAdd(g_deg + dst, 1.0f);
}

// ---------------------------------------------------------------------------
// 2) invert degree
// ---------------------------------------------------------------------------
__global__ void recip_kernel(int n) {
    int i = blockIdx.x * blockDim.x + threadIdx.x;
    if (i < n) g_deg[i] = 1.0f / fmaxf(g_deg[i], 1.0f);
}

// ---------------------------------------------------------------------------
// 2b) prep W: Wcat = [Wl | Wr] -> bf16 hi/lo split, row-major [96][192]
// ---------------------------------------------------------------------------
__global__ void prepw_kernel(const float* __restrict__ Wl,
                             const float* __restrict__ Wr)
{
    int idx = blockIdx.x * blockDim.x + threadIdx.x;
    if (idx >= D * K2) return;
    int n = idx / K2, k = idx % K2;
    float w = (k < D) ? Wl[n * D + k] : Wr[n * D + (k - D)];
    __nv_bfloat16 h = __float2bfloat16(w);
    reinterpret_cast<__nv_bfloat16*>(g_Bhi4)[idx] = h;
    reinterpret_cast<__nv_bfloat16*>(g_Blo4)[idx] =
        __float2bfloat16(w - __bfloat162float(h));
}

// ---------------------------------------------------------------------------
// 3) GEMM via mma.sync bf16 (HMMA fallback path, no sm_103a features):
//      out = relu( A_cat @ Wcat^T + bl ),  A_cat = [agg*invdeg | x]
//    CTA: 128 nodes x 96 outputs, 256 threads = 8 warps, warp tile 32x48.
//    3 passes: Ahi*Bhi + Alo*Bhi + Ahi*Blo, fp32 accumulators.
//    SMEM rows padded to 200 bf16 (400 B) -> conflict-free ldmatrix.
// ---------------------------------------------------------------------------
#define RS    400                  // row stride bytes (200 bf16)
#define SM_AHI 0
#define SM_ALO 51200               // 128*400
#define SM_BHI 102400
#define SM_BLO 140800              // + 96*400
#define SM_TOTAL 179200

__global__ __launch_bounds__(256, 1) void fused_gemm_kernel(
    const float* __restrict__ x, const float* __restrict__ bl,
    float* __restrict__ out, int N)
{
    extern __shared__ char smem[];
    const int tid  = threadIdx.x;
    const int wid  = tid >> 5;
    const int lane = tid & 31;
    const int m0   = blockIdx.x * 128;
    const int mg   = wid & 3;        // m block (32 rows)
    const int ng   = wid >> 2;       // n block (48 cols)

    // --- load W tiles (bf16, pre-split) into padded smem ---
    for (int l = tid; l < 2304; l += 256) {               // 96 rows x 24 uint4
        int n = l / 24, c8 = (l % 24) * 8;                // 8 bf16 = 16 B
        int so = n * RS + c8 * 2;
        *reinterpret_cast<uint4*>(smem + SM_BHI + so) = g_Bhi4[n * 24 + (l % 24)];
        *reinterpret_cast<uint4*>(smem + SM_BLO + so) = g_Blo4[n * 24 + (l % 24)];
    }

    // --- load + convert A: 128 rows x 48 float4 slots (192 fp32) ---
    for (int l = tid; l < 6144; l += 256) {
        int r = l / 48, q = l % 48;
        int node = m0 + r;
        float4 v = make_float4(0.f, 0.f, 0.f, 0.f);
        int kcol;
        if (q < 24) {
            kcol = q * 4;
            if (node < N) {
                v = *reinterpret_cast<const float4*>(g_agg + (size_t)node * D + kcol);
                float inv = g_deg[node];
                v.x *= inv; v.y *= inv; v.z *= inv; v.w *= inv;
            }
        } else {
            kcol = 96 + (q - 24) * 4;
            if (node < N)
                v = *reinterpret_cast<const float4*>(x + (size_t)node * D + (q - 24) * 4);
        }
        uint32_t h01 = pack_bf16x2(v.x, v.y);
        uint32_t h23 = pack_bf16x2(v.z, v.w);
        float r0 = v.x - __uint_as_float(h01 << 16);
        float r1 = v.y - __uint_as_float(h01 & 0xffff0000u);
        float r2 = v.z - __uint_as_float(h23 << 16);
        float r3 = v.w - __uint_as_float(h23 & 0xffff0000u);
        uint32_t l01 = pack_bf16x2(r0, r1);
        uint32_t l23 = pack_bf16x2(r2, r3);
        int so = r * RS + kcol * 2;
        *reinterpret_cast<uint2*>(smem + SM_AHI + so) = make_uint2(h01, h23);
        *reinterpret_cast<uint2*>(smem + SM_ALO + so) = make_uint2(l01, l23);
    }
    __syncthreads();

    // --- mainloop ---
    float acc[2][6][4];
#pragma unroll
    for (int i = 0; i < 2; ++i)
#pragma unroll
        for (int j = 0; j < 6; ++j)
#pragma unroll
            for (int r = 0; r < 4; ++r) acc[i][j][r] = 0.f;

    // per-lane ldmatrix address components
    const int arow  = mg * 32 + (lane & 7) + ((lane >> 3) & 1) * 8;
    const int akoff = (lane >> 4) << 3;
    const int brow  = ng * 48 + (lane & 7) + ((lane >> 4) << 3);
    const int bkoff = ((lane >> 3) & 1) << 3;
    const uint32_t sbase = smem_u32(smem);

#pragma unroll 1
    for (int p = 0; p < 3; ++p) {
        const uint32_t Ab = sbase + (p == 1 ? SM_ALO : SM_AHI);
        const uint32_t Bb = sbase + (p == 2 ? SM_BLO : SM_BHI);
        const uint32_t aAddr = Ab + arow * RS + akoff * 2;
        const uint32_t bAddr = Bb + brow * RS + bkoff * 2;

#pragma unroll
        for (int ks = 0; ks < 12; ++ks) {
            const int kb = ks * 32;               // 16 bf16 = 32 B
            uint32_t a[2][4];
            LDSM_X4(a[0], aAddr + kb);
            LDSM_X4(a[1], aAddr + 16 * RS + kb);
            uint32_t b[3][4];
            LDSM_X4(b[0], bAddr + kb);
            LDSM_X4(b[1], bAddr + 16 * RS + kb);
            LDSM_X4(b[2], bAddr + 32 * RS + kb);
#pragma unroll
            for (int i = 0; i < 2; ++i)
#pragma unroll
                for (int j = 0; j < 6; ++j)
                    mma_bf16(acc[i][j], a[i], b[j >> 1][(j & 1) * 2],
                             b[j >> 1][(j & 1) * 2 + 1]);
        }
    }

    // --- epilogue: bias + relu + float2 stores ---
    const int lrow = lane >> 2;
    const int lcol = (lane & 3) * 2;
#pragma unroll
    for (int i = 0; i < 2; ++i) {
#pragma unroll
        for (int j = 0; j < 6; ++j) {
            int col = ng * 48 + j * 8 + lcol;
            float b0 = __ldg(bl + col);
            float b1 = __ldg(bl + col + 1);
            int row0 = m0 + mg * 32 + i * 16 + lrow;
            if (row0 < N) {
                float2 o = make_float2(fmaxf(acc[i][j][0] + b0, 0.f),
                                       fmaxf(acc[i][j][1] + b1, 0.f));
                *reinterpret_cast<float2*>(out + (size_t)row0 * D + col) = o;
            }
            int row1 = row0 + 8;
            if (row1 < N) {
                float2 o = make_float2(fmaxf(acc[i][j][2] + b0, 0.f),
                                       fmaxf(acc[i][j][3] + b1, 0.f));
                *reinterpret_cast<float2*>(out + (size_t)row1 * D + col) = o;
            }
        }
    }
}

// ---------------------------------------------------------------------------
// kernel_launch
// ---------------------------------------------------------------------------
extern "C" void kernel_launch(void* const* d_in, const int* in_sizes, int n_in,
                              void* d_out, int out_size)
{
    const float* x  = (const float*)d_in[0];
    const int*   ei = (const int*)  d_in[1];
    const float* Wl = (const float*)d_in[2];
    const float* bl = (const float*)d_in[3];
    const float* Wr = (const float*)d_in[4];
    float* out = (float*)d_out;

    const int N = in_sizes[0] / D;
    const int E = in_sizes[1] / 2;

    cudaFuncSetAttribute(fused_gemm_kernel,
                         cudaFuncAttributeMaxDynamicSharedMemorySize, SM_TOTAL);

    zero_kernel<<<2048, 256>>>((N * D) / 4, N);

    dim3 sblk(24, 8);
    scatter_kernel<<<(E + 7) / 8, sblk>>>(x, ei, E);

    recip_kernel<<<(N + 255) / 256, 256>>>(N);
    prepw_kernel<<<(D * K2 + 255) / 256, 256>>>(Wl, Wr);

    fused_gemm_kernel<<<(N + 127) / 128, 256, SM_TOTAL>>>(x, bl, out, N);
}